// round 2
// baseline (speedup 1.0000x reference)
#include <cuda_runtime.h>
#include <math.h>

// ---------------------------------------------------------------------------
// Problem constants (B=2, N=4096, C=256, nc=150, t=3 -> T=4, H=W=64, hid=1024)
// ---------------------------------------------------------------------------

// ---------------------------------------------------------------------------
// Scratch (allocation-free: __device__ globals)
// ---------------------------------------------------------------------------
__device__ float g_xf   [8l*4096*256];     // (B*T, N, C)
__device__ float g_cl   [8l*150*4096];     // (B*T, nc, N)
__device__ float g_Abuf [2l*16384*300];    // (B, TN, 300) = [z*g1 | cl*g2]
__device__ float g_wcomb[300*150];         // [tdt1; tdt2]
__device__ float g_tmp  [2l*16384*150];    // (B, TN, nc) pre-transpose cxz
__device__ float g_soft [8l*150*4096];     // softmax(center)
__device__ float g_cen  [8l*150*256];      // (B*T, nc, C)
__device__ float g_cin  [2l*150*256];      // C_in after gate+LN
__device__ float g_k    [2l*150*256];
__device__ float g_v    [2l*150*256];
__device__ float g_q    [2l*4096*256];
__device__ float g_o    [2l*4096*256];
__device__ float g_oproj[2l*4096*256];
__device__ float g_out1 [2l*4096*256];
__device__ float g_h    [2l*4096*1024];
__device__ float g_h2   [2l*4096*1024];
__device__ float g_h3   [2l*4096*256];

// ---------------------------------------------------------------------------
// Block reductions (blockDim.x == 256)
// ---------------------------------------------------------------------------
__device__ __forceinline__ float blockReduceSum(float v, float* sh) {
    __syncthreads();
    int lane = threadIdx.x & 31, w = threadIdx.x >> 5;
    #pragma unroll
    for (int o = 16; o; o >>= 1) v += __shfl_xor_sync(0xffffffffu, v, o);
    if (lane == 0) sh[w] = v;
    __syncthreads();
    if (w == 0) {
        float t = (lane < 8) ? sh[lane] : 0.f;
        #pragma unroll
        for (int o = 4; o; o >>= 1) t += __shfl_xor_sync(0xffffffffu, t, o);
        if (lane == 0) sh[0] = t;
    }
    __syncthreads();
    return sh[0];
}

__device__ __forceinline__ float blockReduceMax(float v, float* sh) {
    __syncthreads();
    int lane = threadIdx.x & 31, w = threadIdx.x >> 5;
    #pragma unroll
    for (int o = 16; o; o >>= 1) v = fmaxf(v, __shfl_xor_sync(0xffffffffu, v, o));
    if (lane == 0) sh[w] = v;
    __syncthreads();
    if (w == 0) {
        float t = (lane < 8) ? sh[lane] : -1e30f;
        #pragma unroll
        for (int o = 4; o; o >>= 1) t = fmaxf(t, __shfl_xor_sync(0xffffffffu, t, o));
        if (lane == 0) sh[0] = t;
    }
    __syncthreads();
    return sh[0];
}

// ---------------------------------------------------------------------------
// K0: build xf = concat(mem, x) as (B*T, N, C)
// ---------------------------------------------------------------------------
__global__ void build_xf(const float* __restrict__ x, const float* __restrict__ mem) {
    long f = (long)blockIdx.x * blockDim.x + threadIdx.x;   // float4 index
    if (f >= 2097152l) return;                              // 8*4096*256/4
    long bt = f / 262144l;                                  // slab of 4096*256/4
    long rem = f - bt * 262144l;
    long b = bt >> 2, ti = bt & 3;
    const float4* src;
    if (ti < 3) src = (const float4*)mem + (b*3 + ti) * 262144l + rem;
    else        src = (const float4*)x   + b * 262144l + rem;
    ((float4*)g_xf)[f] = *src;
}

// ---------------------------------------------------------------------------
// Generic tiled SGEMM:  C = alpha * (A @ op(B) + bias)
//   gemm_nt: C[m][n] = sum_k A[m*lda+k] * B[n*ldb+k]
//   gemm_nn: C[m][n] = sum_k A[m*lda+k] * B[k*ldb+n]
// batched via blockIdx.z strides.
// ---------------------------------------------------------------------------
#define TM 64
#define TN 64
#define TK 16

__global__ __launch_bounds__(256) void gemm_nt(
    const float* __restrict__ A, const float* __restrict__ Bm,
    const float* __restrict__ bias, float* __restrict__ C,
    int M, int N, int K, int lda, int ldb, int ldc,
    long Astr, long Bstr, long Cstr, float alpha)
{
    A  += (long)blockIdx.z * Astr;
    Bm += (long)blockIdx.z * Bstr;
    C  += (long)blockIdx.z * Cstr;
    __shared__ float As[TK][TM + 4];
    __shared__ float Bs[TK][TN + 4];
    int m0 = blockIdx.y * TM, n0 = blockIdx.x * TN;
    int tid = threadIdx.x;
    int tx = tid & 15, ty = tid >> 4;
    float acc[4][4] = {};
    for (int k0 = 0; k0 < K; k0 += TK) {
        for (int i = tid; i < TM * TK; i += 256) {
            int r = i >> 4, kk = i & 15;
            int m = m0 + r, k = k0 + kk;
            As[kk][r] = (m < M && k < K) ? A[(long)m * lda + k] : 0.f;
        }
        for (int i = tid; i < TN * TK; i += 256) {
            int r = i >> 4, kk = i & 15;
            int n = n0 + r, k = k0 + kk;
            Bs[kk][r] = (n < N && k < K) ? Bm[(long)n * ldb + k] : 0.f;
        }
        __syncthreads();
        #pragma unroll
        for (int kk = 0; kk < TK; kk++) {
            float4 a4 = *(const float4*)&As[kk][ty * 4];
            float4 b4 = *(const float4*)&Bs[kk][tx * 4];
            float a[4] = {a4.x, a4.y, a4.z, a4.w};
            float b[4] = {b4.x, b4.y, b4.z, b4.w};
            #pragma unroll
            for (int i = 0; i < 4; i++)
                #pragma unroll
                for (int j = 0; j < 4; j++)
                    acc[i][j] += a[i] * b[j];
        }
        __syncthreads();
    }
    #pragma unroll
    for (int i = 0; i < 4; i++) {
        int m = m0 + ty * 4 + i;
        if (m >= M) continue;
        #pragma unroll
        for (int j = 0; j < 4; j++) {
            int n = n0 + tx * 4 + j;
            if (n >= N) continue;
            float v = acc[i][j];
            if (bias) v += bias[n];
            C[(long)m * ldc + n] = v * alpha;
        }
    }
}

__global__ __launch_bounds__(256) void gemm_nn(
    const float* __restrict__ A, const float* __restrict__ Bm,
    const float* __restrict__ bias, float* __restrict__ C,
    int M, int N, int K, int lda, int ldb, int ldc,
    long Astr, long Bstr, long Cstr, float alpha)
{
    A  += (long)blockIdx.z * Astr;
    Bm += (long)blockIdx.z * Bstr;
    C  += (long)blockIdx.z * Cstr;
    __shared__ float As[TK][TM + 4];
    __shared__ float Bs[TK][TN + 4];
    int m0 = blockIdx.y * TM, n0 = blockIdx.x * TN;
    int tid = threadIdx.x;
    int tx = tid & 15, ty = tid >> 4;
    float acc[4][4] = {};
    for (int k0 = 0; k0 < K; k0 += TK) {
        for (int i = tid; i < TM * TK; i += 256) {
            int r = i >> 4, kk = i & 15;
            int m = m0 + r, k = k0 + kk;
            As[kk][r] = (m < M && k < K) ? A[(long)m * lda + k] : 0.f;
        }
        for (int i = tid; i < TN * TK; i += 256) {
            int r = i & 63, kk = i >> 6;           // coalesced over n
            int n = n0 + r, k = k0 + kk;
            Bs[kk][r] = (n < N && k < K) ? Bm[(long)k * ldb + n] : 0.f;
        }
        __syncthreads();
        #pragma unroll
        for (int kk = 0; kk < TK; kk++) {
            float4 a4 = *(const float4*)&As[kk][ty * 4];
            float4 b4 = *(const float4*)&Bs[kk][tx * 4];
            float a[4] = {a4.x, a4.y, a4.z, a4.w};
            float b[4] = {b4.x, b4.y, b4.z, b4.w};
            #pragma unroll
            for (int i = 0; i < 4; i++)
                #pragma unroll
                for (int j = 0; j < 4; j++)
                    acc[i][j] += a[i] * b[j];
        }
        __syncthreads();
    }
    #pragma unroll
    for (int i = 0; i < 4; i++) {
        int m = m0 + ty * 4 + i;
        if (m >= M) continue;
        #pragma unroll
        for (int j = 0; j < 4; j++) {
            int n = n0 + tx * 4 + j;
            if (n >= N) continue;
            float v = acc[i][j];
            if (bias) v += bias[n];
            C[(long)m * ldc + n] = v * alpha;
        }
    }
}

// ---------------------------------------------------------------------------
// K2a: cosine gates + build Abuf (B, TN, 300) = [z*g1 | cl*g2]
// ---------------------------------------------------------------------------
__global__ __launch_bounds__(256) void cos_scale(
    const float* __restrict__ z, const float* __restrict__ p1, const float* __restrict__ p2)
{
    __shared__ float sz[150][32];
    __shared__ float scl[150][32];
    __shared__ float g1[32], g2[32];
    int b = blockIdx.y;
    int m0 = blockIdx.x * 32;
    int ti = m0 >> 12, nn0 = m0 & 4095;
    for (int i = threadIdx.x; i < 150 * 32; i += 256) {
        int kk = i >> 5, mm = i & 31;
        sz[kk][mm]  = z[((long)b * 150 + kk) * 16384l + m0 + mm];
        scl[kk][mm] = g_cl[(((long)(b * 4 + ti)) * 150 + kk) * 4096l + nn0 + mm];
    }
    __syncthreads();
    if (threadIdx.x < 32) {
        int mm = threadIdx.x;
        float dz = 0, zz = 0, dc = 0, cc = 0, pp1 = 0, pp2 = 0;
        for (int kk = 0; kk < 150; kk++) {
            float zv = sz[kk][mm], cv = scl[kk][mm];
            float a = p1[kk], bb = p2[kk];
            dz += zv * a; zz += zv * zv;
            dc += cv * bb; cc += cv * cv;
            pp1 += a * a; pp2 += bb * bb;
        }
        float c1 = dz / (fmaxf(sqrtf(zz), 1e-12f) * fmaxf(sqrtf(pp1), 1e-12f));
        float c2 = dc / (fmaxf(sqrtf(cc), 1e-12f) * fmaxf(sqrtf(pp2), 1e-12f));
        g1[mm] = fminf(fmaxf(c1, 0.f), 1.f);
        g2[mm] = fminf(fmaxf(c2, 0.f), 1.f);
    }
    __syncthreads();
    for (int i = threadIdx.x; i < 32 * 300; i += 256) {
        int mm = i / 300, kk = i - mm * 300;
        float v = (kk < 150) ? sz[kk][mm] * g1[mm] : scl[kk - 150][mm] * g2[mm];
        g_Abuf[(((long)b * 16384l) + m0 + mm) * 300 + kk] = v;
    }
}

__global__ void build_wcomb(const float* __restrict__ t1, const float* __restrict__ t2) {
    int i = blockIdx.x * blockDim.x + threadIdx.x;
    if (i < 22500)       g_wcomb[i] = t1[i];
    else if (i < 45000)  g_wcomb[i] = t2[i - 22500];
}

// ---------------------------------------------------------------------------
// K2c: transpose tmp (B,TN,nc) -> out2 (B,nc,TN) and out3 (B,T,nc,N)
// ---------------------------------------------------------------------------
__global__ __launch_bounds__(256) void transpose_out(float* __restrict__ out2, float* __restrict__ out3) {
    __shared__ float t[32][33];
    int b = blockIdx.z;
    int m0 = blockIdx.x * 32;
    int j0 = blockIdx.y * 32;
    int tx = threadIdx.x & 31, ty = threadIdx.x >> 5;
    for (int i = ty; i < 32; i += 8) {
        int j = j0 + tx;
        t[i][tx] = (j < 150) ? g_tmp[((long)b * 16384l + m0 + i) * 150 + j] : 0.f;
    }
    __syncthreads();
    for (int i = ty; i < 32; i += 8) {
        int j = j0 + i;
        if (j < 150) {
            int m = m0 + tx;
            float v = t[tx][i];
            out2[((long)b * 150 + j) * 16384l + m] = v;
            int ti = m >> 12, n = m & 4095;
            out3[(((long)(b * 4 + ti)) * 150 + j) * 4096l + n] = v;
        }
    }
}

// ---------------------------------------------------------------------------
// K3: row softmax (1200 rows of 4096), in = center (out3), out = g_soft
// ---------------------------------------------------------------------------
__global__ __launch_bounds__(256) void softmax_rows(const float* __restrict__ in) {
    __shared__ float sh[32];
    long row = blockIdx.x;
    const float* p = in + row * 4096l;
    float mx = -1e30f;
    for (int i = threadIdx.x; i < 4096; i += 256) mx = fmaxf(mx, p[i]);
    mx = blockReduceMax(mx, sh);
    float s = 0.f;
    for (int i = threadIdx.x; i < 4096; i += 256) s += __expf(p[i] - mx);
    s = blockReduceSum(s, sh);
    float inv = 1.f / s;
    float* q = g_soft + row * 4096l;
    for (int i = threadIdx.x; i < 4096; i += 256) q[i] = __expf(p[i] - mx) * inv;
}

// ---------------------------------------------------------------------------
// K4: gate + C_in + LN  -> g_cin
// ---------------------------------------------------------------------------
__global__ __launch_bounds__(256) void gate_ln(
    const float* __restrict__ sa, const float* __restrict__ sb,
    const float* __restrict__ nw, const float* __restrict__ nb)
{
    __shared__ float sh[32];
    int b = blockIdx.y, k = blockIdx.x, c = threadIdx.x;
    const float* base = g_cen + ((long)(b * 4) * 150 + k) * 256;
    float l = base[3l * 150 * 256 + c];
    float p0 = base[0l * 150 * 256 + c];
    float p1v = base[1l * 150 * 256 + c];
    float p2v = base[2l * 150 * 256 + c];
    float alpha = sa[0], beta = sb[0];
    float ll = blockReduceSum(l * l, sh);
    float nl = sqrtf(ll);
    float g[3];
    float pv[3] = {p0, p1v, p2v};
    #pragma unroll
    for (int ti = 0; ti < 3; ti++) {
        float d  = blockReduceSum(l * pv[ti], sh);
        float nn = blockReduceSum(pv[ti] * pv[ti], sh);
        float denom = fmaxf(nl * sqrtf(nn), 1e-8f);
        float a = beta + alpha * (d / denom);
        g[ti] = 1.f / (1.f + expf(-a));
    }
    float v = l + g[0] * p0 + g[1] * p1v + g[2] * p2v;
    float mean = blockReduceSum(v, sh) * (1.f / 256.f);
    float dlt = v - mean;
    float var = blockReduceSum(dlt * dlt, sh) * (1.f / 256.f);
    g_cin[((long)b * 150 + k) * 256 + c] = dlt * rsqrtf(var + 1e-5f) * nw[c] + nb[c];
}

// ---------------------------------------------------------------------------
// K6: attention (8 heads, nc=150 keys). grid (N/32, 8, B), block 256
// ---------------------------------------------------------------------------
__global__ __launch_bounds__(256) void attn_kernel() {
    __shared__ float sk[150][33];
    __shared__ float sv[150][32];
    __shared__ float sq[32][32];
    __shared__ float sp[8][150];
    int b = blockIdx.z, h = blockIdx.y;
    int n0 = blockIdx.x * 32;
    int tid = threadIdx.x;
    for (int i = tid; i < 150 * 32; i += 256) {
        int kk = i >> 5, d = i & 31;
        long off = ((long)b * 150 + kk) * 256 + h * 32 + d;
        sk[kk][d] = g_k[off];
        sv[kk][d] = g_v[off];
    }
    for (int i = tid; i < 1024; i += 256) {
        int nn = i >> 5, d = i & 31;
        sq[nn][d] = g_q[((long)(b * 4096) + n0 + nn) * 256 + h * 32 + d];
    }
    __syncthreads();
    int w = tid >> 5, lane = tid & 31;
    for (int nn = w; nn < 32; nn += 8) {
        float e[5];
        float mx = -1e30f;
        #pragma unroll
        for (int s = 0; s < 5; s++) {
            int kk = lane + s * 32;
            float dot = -1e30f;
            if (kk < 150) {
                dot = 0.f;
                #pragma unroll
                for (int d = 0; d < 32; d++) dot += sq[nn][d] * sk[kk][d];
            }
            e[s] = dot;
            mx = fmaxf(mx, dot);
        }
        #pragma unroll
        for (int o = 16; o; o >>= 1) mx = fmaxf(mx, __shfl_xor_sync(0xffffffffu, mx, o));
        float sum = 0.f;
        #pragma unroll
        for (int s = 0; s < 5; s++) {
            int kk = lane + s * 32;
            float ev = (kk < 150) ? __expf(e[s] - mx) : 0.f;
            e[s] = ev;
            sum += ev;
        }
        #pragma unroll
        for (int o = 16; o; o >>= 1) sum += __shfl_xor_sync(0xffffffffu, sum, o);
        float inv = 1.f / sum;
        #pragma unroll
        for (int s = 0; s < 5; s++) {
            int kk = lane + s * 32;
            if (kk < 150) sp[w][kk] = e[s] * inv;
        }
        __syncwarp();
        float acc = 0.f;
        for (int kk = 0; kk < 150; kk++) acc += sp[w][kk] * sv[kk][lane];
        g_o[((long)(b * 4096) + n0 + nn) * 256 + h * 32 + lane] = acc;
        __syncwarp();
    }
}

// ---------------------------------------------------------------------------
// K7 / K11: out = resid + LN(xin)   (rows of 256)
// ---------------------------------------------------------------------------
__global__ __launch_bounds__(256) void add_ln(
    const float* __restrict__ resid, const float* __restrict__ xin,
    const float* __restrict__ nw, const float* __restrict__ nb, float* __restrict__ out)
{
    __shared__ float sh[32];
    long row = blockIdx.x;
    float v = xin[row * 256 + threadIdx.x];
    float mean = blockReduceSum(v, sh) * (1.f / 256.f);
    float d = v - mean;
    float var = blockReduceSum(d * d, sh) * (1.f / 256.f);
    out[row * 256 + threadIdx.x] =
        resid[row * 256 + threadIdx.x] + d * rsqrtf(var + 1e-5f) * nw[threadIdx.x] + nb[threadIdx.x];
}

// ---------------------------------------------------------------------------
// K9: depthwise 3x3 conv (SAME) on (B,1024,64,64) + bias + exact GELU
// grid: 512 blocks = B * (4096/16) token-chunks, block 256 (each thread 4 ch)
// ---------------------------------------------------------------------------
__global__ __launch_bounds__(256) void dwconv(
    const float* __restrict__ dw, const float* __restrict__ dwb)
{
    int blk = blockIdx.x;
    int b = blk >> 8;
    int chunk = blk & 255;
    int y = chunk >> 2;
    int x0 = (chunk & 3) * 16;
    int ch0 = threadIdx.x * 4;
    float w[3][3][4];
    #pragma unroll
    for (int ky = 0; ky < 3; ky++)
        #pragma unroll
        for (int kx = 0; kx < 3; kx++)
            #pragma unroll
            for (int c = 0; c < 4; c++)
                w[ky][kx][c] = dw[(long)(ch0 + c) * 9 + ky * 3 + kx];
    float bias4[4];
    #pragma unroll
    for (int c = 0; c < 4; c++) bias4[c] = dwb[ch0 + c];
    for (int xi = 0; xi < 16; xi++) {
        int xx = x0 + xi;
        float acc[4] = {0.f, 0.f, 0.f, 0.f};
        #pragma unroll
        for (int ky = 0; ky < 3; ky++) {
            int yy = y + ky - 1;
            if (yy < 0 || yy > 63) continue;
            #pragma unroll
            for (int kx = 0; kx < 3; kx++) {
                int xk = xx + kx - 1;
                if (xk < 0 || xk > 63) continue;
                const float4 s = *(const float4*)(g_h + ((long)b * 4096 + yy * 64 + xk) * 1024 + ch0);
                acc[0] += s.x * w[ky][kx][0];
                acc[1] += s.y * w[ky][kx][1];
                acc[2] += s.z * w[ky][kx][2];
                acc[3] += s.w * w[ky][kx][3];
            }
        }
        float4 r;
        float v0 = acc[0] + bias4[0]; r.x = v0 * normcdff(v0);
        float v1 = acc[1] + bias4[1]; r.y = v1 * normcdff(v1);
        float v2 = acc[2] + bias4[2]; r.z = v2 * normcdff(v2);
        float v3 = acc[3] + bias4[3]; r.w = v3 * normcdff(v3);
        *(float4*)(g_h2 + ((long)b * 4096 + y * 64 + xx) * 1024 + ch0) = r;
    }
}

// ---------------------------------------------------------------------------
// Host launcher
// ---------------------------------------------------------------------------
extern "C" void kernel_launch(void* const* d_in, const int* in_sizes, int n_in,
                              void* d_out, int out_size)
{
    const float* x       = (const float*)d_in[0];
    const float* z       = (const float*)d_in[1];
    const float* mem     = (const float*)d_in[2];
    const float* cw      = (const float*)d_in[3];
    const float* p1      = (const float*)d_in[4];
    const float* tdt1    = (const float*)d_in[5];
    const float* p2      = (const float*)d_in[6];
    const float* tdt2    = (const float*)d_in[7];
    const float* sa      = (const float*)d_in[8];
    const float* sb      = (const float*)d_in[9];
    const float* q_w     = (const float*)d_in[10];
    const float* q_b     = (const float*)d_in[11];
    const float* k_w     = (const float*)d_in[12];
    const float* k_b     = (const float*)d_in[13];
    const float* v_w     = (const float*)d_in[14];
    const float* v_b     = (const float*)d_in[15];
    const float* proj_w  = (const float*)d_in[16];
    const float* proj_b  = (const float*)d_in[17];
    const float* norm_w  = (const float*)d_in[18];
    const float* norm_b  = (const float*)d_in[19];
    const float* fc1_w   = (const float*)d_in[20];
    const float* fc1_b   = (const float*)d_in[21];
    const float* dw_w    = (const float*)d_in[22];
    const float* dw_b    = (const float*)d_in[23];
    const float* fc2_w   = (const float*)d_in[24];
    const float* fc2_b   = (const float*)d_in[25];

    float* out  = (float*)d_out;                 // (B,N,C)
    float* out2 = out + 2097152l;                // cluster_x_z (B,nc,TN)
    float* out3 = out2 + 4915200l;               // assigned (B,T,nc,N)

    float *xf, *cl, *Abuf, *wcomb, *tmp, *soft, *cen, *cin, *kb, *vb, *qb, *ob, *opj, *o1, *hb, *h2, *h3;
    cudaGetSymbolAddress((void**)&xf,   g_xf);
    cudaGetSymbolAddress((void**)&cl,   g_cl);
    cudaGetSymbolAddress((void**)&Abuf, g_Abuf);
    cudaGetSymbolAddress((void**)&wcomb,g_wcomb);
    cudaGetSymbolAddress((void**)&tmp,  g_tmp);
    cudaGetSymbolAddress((void**)&soft, g_soft);
    cudaGetSymbolAddress((void**)&cen,  g_cen);
    cudaGetSymbolAddress((void**)&cin,  g_cin);
    cudaGetSymbolAddress((void**)&kb,   g_k);
    cudaGetSymbolAddress((void**)&vb,   g_v);
    cudaGetSymbolAddress((void**)&qb,   g_q);
    cudaGetSymbolAddress((void**)&ob,   g_o);
    cudaGetSymbolAddress((void**)&opj,  g_oproj);
    cudaGetSymbolAddress((void**)&o1,   g_out1);
    cudaGetSymbolAddress((void**)&hb,   g_h);
    cudaGetSymbolAddress((void**)&h2,   g_h2);
    cudaGetSymbolAddress((void**)&h3,   g_h3);

    const float qscale = 0.17677669529663687f;   // 1/sqrt(32)

    // 1. xf
    build_xf<<<8192, 256>>>(x, mem);

    // 2. cl[bt,k,n] = cw @ xf[bt]^T   (M=150, N=4096, K=256, batched 8)
    gemm_nt<<<dim3(64, 3, 8), 256>>>(cw, xf, nullptr, cl,
        150, 4096, 256, 256, 256, 4096, 0l, 4096l * 256, 150l * 4096, 1.f);

    // 3. cosine gates + Abuf
    cos_scale<<<dim3(512, 2), 256>>>(z, p1, p2);

    // 4. Wcomb = [tdt1; tdt2]
    build_wcomb<<<176, 256>>>(tdt1, tdt2);

    // 5. tmp = 0.5 * Abuf @ Wcomb  (M=16384, N=150, K=300, batched 2)
    gemm_nn<<<dim3(3, 256, 2), 256>>>(Abuf, wcomb, nullptr, tmp,
        16384, 150, 300, 300, 150, 150, 16384l * 300, 0l, 16384l * 150, 0.5f);

    // 6. transpose -> out2 (cluster_x_z), out3 (assigned/center)
    transpose_out<<<dim3(512, 5, 2), 256>>>(out2, out3);

    // 7. softmax over N -> g_soft
    softmax_rows<<<1200, 256>>>(out3);

    // 8. cen = soft @ xf  (M=150, N=256, K=4096, batched 8)
    gemm_nn<<<dim3(4, 3, 8), 256>>>(soft, xf, nullptr, cen,
        150, 256, 4096, 4096, 256, 256, 150l * 4096, 4096l * 256, 150l * 256, 1.f);

    // 9. gate + C_in + LN
    gate_ln<<<dim3(150, 2), 256>>>(sa, sb, norm_w, norm_b);

    // 10/11. k, v projections (M=300)
    gemm_nt<<<dim3(4, 5, 1), 256>>>(cin, k_w, k_b, kb,
        300, 256, 256, 256, 256, 256, 0l, 0l, 0l, 1.f);
    gemm_nt<<<dim3(4, 5, 1), 256>>>(cin, v_w, v_b, vb,
        300, 256, 256, 256, 256, 256, 0l, 0l, 0l, 1.f);

    // 12. q projection (scaled)
    gemm_nt<<<dim3(4, 128, 1), 256>>>(x, q_w, q_b, qb,
        8192, 256, 256, 256, 256, 256, 0l, 0l, 0l, qscale);

    // 13. attention
    attn_kernel<<<dim3(128, 8, 2), 256>>>();

    // 14. output projection
    gemm_nt<<<dim3(4, 128, 1), 256>>>(ob, proj_w, proj_b, opj,
        8192, 256, 256, 256, 256, 256, 0l, 0l, 0l, 1.f);

    // 15. out1 = x + LN(oproj)
    add_ln<<<8192, 256>>>(x, opj, norm_w, norm_b, o1);

    // 16. fc1
    gemm_nt<<<dim3(16, 128, 1), 256>>>(o1, fc1_w, fc1_b, hb,
        8192, 1024, 256, 256, 256, 1024, 0l, 0l, 0l, 1.f);

    // 17. depthwise conv + bias + gelu
    dwconv<<<512, 256>>>(dw_w, dw_b);

    // 18. fc2
    gemm_nt<<<dim3(4, 128, 1), 256>>>(h2, fc2_w, fc2_b, h3,
        8192, 256, 1024, 1024, 1024, 256, 0l, 0l, 0l, 1.f);

    // 19. final out = out1 + LN(h3)
    add_ln<<<8192, 256>>>(o1, h3, norm_w, norm_b, out);
}

// round 5
// speedup vs baseline: 1.5765x; 1.5765x over previous
#include <cuda_runtime.h>
#include <math.h>

// ---------------------------------------------------------------------------
// Problem constants (B=2, N=4096, C=256, nc=150, t=3 -> T=4, H=W=64, hid=1024)
// ---------------------------------------------------------------------------

// ---------------------------------------------------------------------------
// Scratch (allocation-free: __device__ globals)
// ---------------------------------------------------------------------------
__device__ float g_xf   [8l*4096*256];       // (B*T, N, C)
__device__ float g_clT  [8l*4096*150];       // (B*T, N, nc)  row-major over nc
__device__ float g_Abuf [2l*16384*300];      // (B, TN, 300) = [z*g1 | cl*g2]
__device__ float g_wcomb[300*152 + 64];      // [tdt1; tdt2], ld=152 (16B-aligned rows)
__device__ float g_tmp  [2l*16384*150];      // (B, TN, nc) pre-transpose cxz
__device__ float g_soft [8l*150*4096];       // softmax(center)
__device__ float g_cen  [8l*150*256];        // (B*T, nc, C)
__device__ float g_cin  [2l*150*256];        // C_in after gate+LN
__device__ float g_k    [2l*150*256];
__device__ float g_v    [2l*150*256];
__device__ float g_q    [2l*4096*256];
__device__ float g_o    [2l*4096*256];
__device__ float g_oproj[2l*4096*256];
__device__ float g_out1 [2l*4096*256];
__device__ float g_h    [2l*4096*1024];
__device__ float g_h2   [2l*4096*1024];
__device__ float g_h3   [2l*4096*256];

// ---------------------------------------------------------------------------
// f32x2 helpers (packed fp32 FMA — 2x fp32 throughput on sm_103a)
// ---------------------------------------------------------------------------
__device__ __forceinline__ void ffma2(unsigned long long& d,
                                      unsigned long long a, unsigned long long b) {
    asm("fma.rn.f32x2 %0, %1, %2, %0;" : "+l"(d) : "l"(a), "l"(b));
}
__device__ __forceinline__ unsigned long long pack2(float x) {
    unsigned long long r;
    unsigned u = __float_as_uint(x);
    asm("mov.b64 %0, {%1, %1};" : "=l"(r) : "r"(u));
    return r;
}

// ---------------------------------------------------------------------------
// Fast SGEMM: C = alpha * (A @ op(B) + bias)
//   TRANSB=1: B[n][k] (NT)    TRANSB=0: B[k][n] (NN)
//   ATOMIC=1: atomicAdd into C (for split-K), bias ignored
// BM=128, BN=64, BK=16, 256 threads, 4x8 microtile (f32x2 pairs), double-buffer.
// Requires lda%4==0 and ldb%4==0 (16B-aligned vector loads).
// blockIdx.z = batch * ksplit + ks;  K segment = [ks*kLen, ks*kLen+kLen)
// ---------------------------------------------------------------------------
template<int TRANSB, int ATOMIC>
__global__ __launch_bounds__(256) void fgemm(
    const float* __restrict__ A, const float* __restrict__ Bm,
    const float* __restrict__ bias, float* __restrict__ C,
    int M, int N, int K, int lda, int ldb, int ldc,
    long Astr, long Bstr, long Cstr, float alpha,
    int ksplit, int kLen)
{
    int zb = blockIdx.z;
    int batch = zb / ksplit;
    int ks = zb - batch * ksplit;
    int kStart = ks * kLen;
    int kEnd = kStart + kLen; if (kEnd > K) kEnd = K;

    A  += (long)batch * Astr;
    Bm += (long)batch * Bstr;
    C  += (long)batch * Cstr;

    __shared__ __align__(16) float As[2][16][132];
    __shared__ __align__(16) float Bs[2][16][68];

    int m0 = blockIdx.y * 128, n0 = blockIdx.x * 64;
    int tid = threadIdx.x;
    int ty = tid >> 3;          // 0..31 -> rows m0 + ty*4 .. +3
    int tx = tid & 7;           // 0..7  -> cols n0 + tx*8 .. +7

    unsigned long long acc[4][4];
    #pragma unroll
    for (int i = 0; i < 4; i++)
        #pragma unroll
        for (int j = 0; j < 4; j++) acc[i][j] = 0ull;

    int nk = (kEnd - kStart + 15) >> 4;

    // load indices
    int am  = tid >> 2;         // 0..63 (and +64)
    int akq = tid & 3;          // float4 slot in k
    int bn  = tid >> 2;         // NT: B row 0..63
    int bkk = tid >> 4;         // NN: k row 0..15
    int bn4 = tid & 15;         // NN: float4 col
    const float4 z4 = make_float4(0.f, 0.f, 0.f, 0.f);

    // ---- preload chunk 0 into buffer 0
    {
        int kb = kStart;
        float4 ra0 = z4, ra1 = z4, rb0 = z4;
        int k = kb + akq * 4;
        int mA0 = m0 + am, mA1 = m0 + am + 64;
        if (k < kEnd) {
            if (mA0 < M) ra0 = *(const float4*)&A[(long)mA0 * lda + k];
            if (mA1 < M) ra1 = *(const float4*)&A[(long)mA1 * lda + k];
        }
        if (TRANSB) {
            int n = n0 + bn;
            if (k < kEnd && n < N) rb0 = *(const float4*)&Bm[(long)n * ldb + k];
        } else {
            int kg = kb + bkk;
            if (kg < kEnd) rb0 = *(const float4*)&Bm[(long)kg * ldb + n0 + bn4 * 4];
        }
        As[0][akq*4+0][am] = ra0.x; As[0][akq*4+1][am] = ra0.y;
        As[0][akq*4+2][am] = ra0.z; As[0][akq*4+3][am] = ra0.w;
        As[0][akq*4+0][am+64] = ra1.x; As[0][akq*4+1][am+64] = ra1.y;
        As[0][akq*4+2][am+64] = ra1.z; As[0][akq*4+3][am+64] = ra1.w;
        if (TRANSB) {
            Bs[0][akq*4+0][bn] = rb0.x; Bs[0][akq*4+1][bn] = rb0.y;
            Bs[0][akq*4+2][bn] = rb0.z; Bs[0][akq*4+3][bn] = rb0.w;
        } else {
            *(float4*)&Bs[0][bkk][bn4*4] = rb0;
        }
    }
    __syncthreads();

    int cur = 0;
    for (int c = 0; c < nk; c++) {
        // prefetch next chunk into registers (overlaps with compute)
        float4 ra0 = z4, ra1 = z4, rb0 = z4;
        if (c + 1 < nk) {
            int kb = kStart + (c + 1) * 16;
            int k = kb + akq * 4;
            int mA0 = m0 + am, mA1 = m0 + am + 64;
            if (k < kEnd) {
                if (mA0 < M) ra0 = *(const float4*)&A[(long)mA0 * lda + k];
                if (mA1 < M) ra1 = *(const float4*)&A[(long)mA1 * lda + k];
            }
            if (TRANSB) {
                int n = n0 + bn;
                if (k < kEnd && n < N) rb0 = *(const float4*)&Bm[(long)n * ldb + k];
            } else {
                int kg = kb + bkk;
                if (kg < kEnd) rb0 = *(const float4*)&Bm[(long)kg * ldb + n0 + bn4 * 4];
            }
        }
        // compute current chunk
        #pragma unroll
        for (int kk = 0; kk < 16; kk++) {
            float4 a4 = *(const float4*)&As[cur][kk][ty * 4];
            ulonglong2 bA = *(const ulonglong2*)&Bs[cur][kk][tx * 8];
            ulonglong2 bB = *(const ulonglong2*)&Bs[cur][kk][tx * 8 + 4];
            float av[4] = {a4.x, a4.y, a4.z, a4.w};
            #pragma unroll
            for (int i = 0; i < 4; i++) {
                unsigned long long a2 = pack2(av[i]);
                ffma2(acc[i][0], a2, bA.x);
                ffma2(acc[i][1], a2, bA.y);
                ffma2(acc[i][2], a2, bB.x);
                ffma2(acc[i][3], a2, bB.y);
            }
        }
        if (c + 1 < nk) {
            int nx = cur ^ 1;
            As[nx][akq*4+0][am] = ra0.x; As[nx][akq*4+1][am] = ra0.y;
            As[nx][akq*4+2][am] = ra0.z; As[nx][akq*4+3][am] = ra0.w;
            As[nx][akq*4+0][am+64] = ra1.x; As[nx][akq*4+1][am+64] = ra1.y;
            As[nx][akq*4+2][am+64] = ra1.z; As[nx][akq*4+3][am+64] = ra1.w;
            if (TRANSB) {
                Bs[nx][akq*4+0][bn] = rb0.x; Bs[nx][akq*4+1][bn] = rb0.y;
                Bs[nx][akq*4+2][bn] = rb0.z; Bs[nx][akq*4+3][bn] = rb0.w;
            } else {
                *(float4*)&Bs[nx][bkk][bn4*4] = rb0;
            }
            __syncthreads();
            cur = nx;
        }
    }

    // epilogue
    #pragma unroll
    for (int i = 0; i < 4; i++) {
        int m = m0 + ty * 4 + i;
        if (m >= M) continue;
        #pragma unroll
        for (int j = 0; j < 4; j++) {
            int n = n0 + tx * 8 + j * 2;
            unsigned long long v = acc[i][j];
            float lo = __uint_as_float((unsigned)(v & 0xffffffffu));
            float hi = __uint_as_float((unsigned)(v >> 32));
            if (ATOMIC) {
                if (n < N)     atomicAdd(&C[(long)m * ldc + n],     lo * alpha);
                if (n + 1 < N) atomicAdd(&C[(long)m * ldc + n + 1], hi * alpha);
            } else {
                if (n < N) {
                    float t = lo + (bias ? bias[n] : 0.f);
                    C[(long)m * ldc + n] = t * alpha;
                }
                if (n + 1 < N) {
                    float t = hi + (bias ? bias[n + 1] : 0.f);
                    C[(long)m * ldc + n + 1] = t * alpha;
                }
            }
        }
    }
}

// ---------------------------------------------------------------------------
// Block reductions (blockDim.x == 256)
// ---------------------------------------------------------------------------
__device__ __forceinline__ float blockReduceSum(float v, float* sh) {
    __syncthreads();
    int lane = threadIdx.x & 31, w = threadIdx.x >> 5;
    #pragma unroll
    for (int o = 16; o; o >>= 1) v += __shfl_xor_sync(0xffffffffu, v, o);
    if (lane == 0) sh[w] = v;
    __syncthreads();
    if (w == 0) {
        float t = (lane < 8) ? sh[lane] : 0.f;
        #pragma unroll
        for (int o = 4; o; o >>= 1) t += __shfl_xor_sync(0xffffffffu, t, o);
        if (lane == 0) sh[0] = t;
    }
    __syncthreads();
    return sh[0];
}

__device__ __forceinline__ float blockReduceMax(float v, float* sh) {
    __syncthreads();
    int lane = threadIdx.x & 31, w = threadIdx.x >> 5;
    #pragma unroll
    for (int o = 16; o; o >>= 1) v = fmaxf(v, __shfl_xor_sync(0xffffffffu, v, o));
    if (lane == 0) sh[w] = v;
    __syncthreads();
    if (w == 0) {
        float t = (lane < 8) ? sh[lane] : -1e30f;
        #pragma unroll
        for (int o = 4; o; o >>= 1) t = fmaxf(t, __shfl_xor_sync(0xffffffffu, t, o));
        if (lane == 0) sh[0] = t;
    }
    __syncthreads();
    return sh[0];
}

// ---------------------------------------------------------------------------
// build xf = concat(mem, x) as (B*T, N, C)
// ---------------------------------------------------------------------------
__global__ void build_xf(const float* __restrict__ x, const float* __restrict__ mem) {
    long f = (long)blockIdx.x * blockDim.x + threadIdx.x;   // float4 index
    if (f >= 2097152l) return;                              // 8*4096*256/4
    long bt = f / 262144l;
    long rem = f - bt * 262144l;
    long b = bt >> 2, ti = bt & 3;
    const float4* src;
    if (ti < 3) src = (const float4*)mem + (b*3 + ti) * 262144l + rem;
    else        src = (const float4*)x   + b * 262144l + rem;
    ((float4*)g_xf)[f] = *src;
}

// ---------------------------------------------------------------------------
// cosine gates + build Abuf (B, TN, 300) = [z*g1 | clT*g2]
// ---------------------------------------------------------------------------
__global__ __launch_bounds__(256) void cos_scale(
    const float* __restrict__ z, const float* __restrict__ p1, const float* __restrict__ p2)
{
    __shared__ float sz[150][32];
    __shared__ float scl[32][161];
    __shared__ float g1[32], g2[32];
    int b = blockIdx.y;
    int m0 = blockIdx.x * 32;
    int ti = m0 >> 12, nn0 = m0 & 4095;
    for (int i = threadIdx.x; i < 150 * 32; i += 256) {
        int kk = i >> 5, mm = i & 31;
        sz[kk][mm] = z[((long)b * 150 + kk) * 16384l + m0 + mm];
    }
    for (int i = threadIdx.x; i < 32 * 160; i += 256) {
        int mm = i / 160, col = i - mm * 160;
        if (col < 150)
            scl[mm][col] = g_clT[(((long)(b * 4 + ti)) * 4096 + nn0 + mm) * 150 + col];
    }
    __syncthreads();
    if (threadIdx.x < 32) {
        int mm = threadIdx.x;
        float dz = 0, zz = 0, dc = 0, cc = 0, pp1 = 0, pp2 = 0;
        for (int kk = 0; kk < 150; kk++) {
            float zv = sz[kk][mm], cv = scl[mm][kk];
            float a = p1[kk], bb = p2[kk];
            dz += zv * a; zz += zv * zv;
            dc += cv * bb; cc += cv * cv;
            pp1 += a * a; pp2 += bb * bb;
        }
        float c1 = dz / (fmaxf(sqrtf(zz), 1e-12f) * fmaxf(sqrtf(pp1), 1e-12f));
        float c2 = dc / (fmaxf(sqrtf(cc), 1e-12f) * fmaxf(sqrtf(pp2), 1e-12f));
        g1[mm] = fminf(fmaxf(c1, 0.f), 1.f);
        g2[mm] = fminf(fmaxf(c2, 0.f), 1.f);
    }
    __syncthreads();
    for (int i = threadIdx.x; i < 32 * 300; i += 256) {
        int mm = i / 300, kk = i - mm * 300;
        float v = (kk < 150) ? sz[kk][mm] * g1[mm] : scl[mm][kk - 150] * g2[mm];
        g_Abuf[(((long)b * 16384l) + m0 + mm) * 300 + kk] = v;
    }
}

// wcomb with ld=152 (zero-padded cols 150..151 and 64-float tail)
__global__ void build_wcomb(const float* __restrict__ t1, const float* __restrict__ t2) {
    int i = blockIdx.x * blockDim.x + threadIdx.x;
    if (i >= 300 * 152 + 64) return;
    float v = 0.f;
    if (i < 300 * 152) {
        int row = i / 152, col = i - row * 152;
        if (col < 150)
            v = (row < 150) ? t1[row * 150 + col] : t2[(row - 150) * 150 + col];
    }
    g_wcomb[i] = v;
}

__global__ void zero_cen() {
    int i = blockIdx.x * 256 + threadIdx.x;
    if (i < 76800) ((float4*)g_cen)[i] = make_float4(0.f, 0.f, 0.f, 0.f);
}

// ---------------------------------------------------------------------------
// transpose tmp (B,TN,nc) -> out2 (B,nc,TN) and out3 (B,T,nc,N)
// ---------------------------------------------------------------------------
__global__ __launch_bounds__(256) void transpose_out(float* __restrict__ out2, float* __restrict__ out3) {
    __shared__ float t[32][33];
    int b = blockIdx.z;
    int m0 = blockIdx.x * 32;
    int j0 = blockIdx.y * 32;
    int tx = threadIdx.x & 31, ty = threadIdx.x >> 5;
    for (int i = ty; i < 32; i += 8) {
        int j = j0 + tx;
        t[i][tx] = (j < 150) ? g_tmp[((long)b * 16384l + m0 + i) * 150 + j] : 0.f;
    }
    __syncthreads();
    for (int i = ty; i < 32; i += 8) {
        int j = j0 + i;
        if (j < 150) {
            int m = m0 + tx;
            float v = t[tx][i];
            out2[((long)b * 150 + j) * 16384l + m] = v;
            int ti = m >> 12, n = m & 4095;
            out3[(((long)(b * 4 + ti)) * 150 + j) * 4096l + n] = v;
        }
    }
}

// ---------------------------------------------------------------------------
// row softmax (1200 rows of 4096)
// ---------------------------------------------------------------------------
__global__ __launch_bounds__(256) void softmax_rows(const float* __restrict__ in) {
    __shared__ float sh[32];
    long row = blockIdx.x;
    const float* p = in + row * 4096l;
    float mx = -1e30f;
    for (int i = threadIdx.x; i < 4096; i += 256) mx = fmaxf(mx, p[i]);
    mx = blockReduceMax(mx, sh);
    float s = 0.f;
    for (int i = threadIdx.x; i < 4096; i += 256) s += __expf(p[i] - mx);
    s = blockReduceSum(s, sh);
    float inv = 1.f / s;
    float* q = g_soft + row * 4096l;
    for (int i = threadIdx.x; i < 4096; i += 256) q[i] = __expf(p[i] - mx) * inv;
}

// ---------------------------------------------------------------------------
// gate + C_in + LN  -> g_cin
// ---------------------------------------------------------------------------
__global__ __launch_bounds__(256) void gate_ln(
    const float* __restrict__ sa, const float* __restrict__ sb,
    const float* __restrict__ nw, const float* __restrict__ nb)
{
    __shared__ float sh[32];
    int b = blockIdx.y, k = blockIdx.x, c = threadIdx.x;
    const float* base = g_cen + ((long)(b * 4) * 150 + k) * 256;
    float l = base[3l * 150 * 256 + c];
    float p0 = base[0l * 150 * 256 + c];
    float p1v = base[1l * 150 * 256 + c];
    float p2v = base[2l * 150 * 256 + c];
    float alpha = sa[0], beta = sb[0];
    float ll = blockReduceSum(l * l, sh);
    float nl = sqrtf(ll);
    float g[3];
    float pv[3] = {p0, p1v, p2v};
    #pragma unroll
    for (int ti = 0; ti < 3; ti++) {
        float d  = blockReduceSum(l * pv[ti], sh);
        float nn = blockReduceSum(pv[ti] * pv[ti], sh);
        float denom = fmaxf(nl * sqrtf(nn), 1e-8f);
        float a = beta + alpha * (d / denom);
        g[ti] = 1.f / (1.f + expf(-a));
    }
    float v = l + g[0] * p0 + g[1] * p1v + g[2] * p2v;
    float mean = blockReduceSum(v, sh) * (1.f / 256.f);
    float dlt = v - mean;
    float var = blockReduceSum(dlt * dlt, sh) * (1.f / 256.f);
    g_cin[((long)b * 150 + k) * 256 + c] = dlt * rsqrtf(var + 1e-5f) * nw[c] + nb[c];
}

// ---------------------------------------------------------------------------
// attention (8 heads, nc=150 keys). grid (N/32, 8, B), block 256
// ---------------------------------------------------------------------------
__global__ __launch_bounds__(256) void attn_kernel() {
    __shared__ float sk[150][33];
    __shared__ float sv[150][32];
    __shared__ float sq[32][32];
    __shared__ float sp[8][150];
    int b = blockIdx.z, h = blockIdx.y;
    int n0 = blockIdx.x * 32;
    int tid = threadIdx.x;
    for (int i = tid; i < 150 * 32; i += 256) {
        int kk = i >> 5, d = i & 31;
        long off = ((long)b * 150 + kk) * 256 + h * 32 + d;
        sk[kk][d] = g_k[off];
        sv[kk][d] = g_v[off];
    }
    for (int i = tid; i < 1024; i += 256) {
        int nn = i >> 5, d = i & 31;
        sq[nn][d] = g_q[((long)(b * 4096) + n0 + nn) * 256 + h * 32 + d];
    }
    __syncthreads();
    int w = tid >> 5, lane = tid & 31;
    for (int nn = w; nn < 32; nn += 8) {
        float e[5];
        float mx = -1e30f;
        #pragma unroll
        for (int s = 0; s < 5; s++) {
            int kk = lane + s * 32;
            float dot = -1e30f;
            if (kk < 150) {
                dot = 0.f;
                #pragma unroll
                for (int d = 0; d < 32; d++) dot += sq[nn][d] * sk[kk][d];
            }
            e[s] = dot;
            mx = fmaxf(mx, dot);
        }
        #pragma unroll
        for (int o = 16; o; o >>= 1) mx = fmaxf(mx, __shfl_xor_sync(0xffffffffu, mx, o));
        float sum = 0.f;
        #pragma unroll
        for (int s = 0; s < 5; s++) {
            int kk = lane + s * 32;
            float ev = (kk < 150) ? __expf(e[s] - mx) : 0.f;
            e[s] = ev;
            sum += ev;
        }
        #pragma unroll
        for (int o = 16; o; o >>= 1) sum += __shfl_xor_sync(0xffffffffu, sum, o);
        float inv = 1.f / sum;
        #pragma unroll
        for (int s = 0; s < 5; s++) {
            int kk = lane + s * 32;
            if (kk < 150) sp[w][kk] = e[s] * inv;
        }
        __syncwarp();
        float acc = 0.f;
        for (int kk = 0; kk < 150; kk++) acc += sp[w][kk] * sv[kk][lane];
        g_o[((long)(b * 4096) + n0 + nn) * 256 + h * 32 + lane] = acc;
        __syncwarp();
    }
}

// ---------------------------------------------------------------------------
// out = resid + LN(xin)   (rows of 256)
// ---------------------------------------------------------------------------
__global__ __launch_bounds__(256) void add_ln(
    const float* __restrict__ resid, const float* __restrict__ xin,
    const float* __restrict__ nw, const float* __restrict__ nb, float* __restrict__ out)
{
    __shared__ float sh[32];
    long row = blockIdx.x;
    float v = xin[row * 256 + threadIdx.x];
    float mean = blockReduceSum(v, sh) * (1.f / 256.f);
    float d = v - mean;
    float var = blockReduceSum(d * d, sh) * (1.f / 256.f);
    out[row * 256 + threadIdx.x] =
        resid[row * 256 + threadIdx.x] + d * rsqrtf(var + 1e-5f) * nw[threadIdx.x] + nb[threadIdx.x];
}

// ---------------------------------------------------------------------------
// depthwise 3x3 conv (SAME) on (B,1024,64,64) + bias + exact GELU
// ---------------------------------------------------------------------------
__global__ __launch_bounds__(256) void dwconv(
    const float* __restrict__ dw, const float* __restrict__ dwb)
{
    int blk = blockIdx.x;
    int b = blk >> 8;
    int chunk = blk & 255;
    int y = chunk >> 2;
    int x0 = (chunk & 3) * 16;
    int ch0 = threadIdx.x * 4;
    float w[3][3][4];
    #pragma unroll
    for (int ky = 0; ky < 3; ky++)
        #pragma unroll
        for (int kx = 0; kx < 3; kx++)
            #pragma unroll
            for (int c = 0; c < 4; c++)
                w[ky][kx][c] = dw[(long)(ch0 + c) * 9 + ky * 3 + kx];
    float bias4[4];
    #pragma unroll
    for (int c = 0; c < 4; c++) bias4[c] = dwb[ch0 + c];
    for (int xi = 0; xi < 16; xi++) {
        int xx = x0 + xi;
        float acc[4] = {0.f, 0.f, 0.f, 0.f};
        #pragma unroll
        for (int ky = 0; ky < 3; ky++) {
            int yy = y + ky - 1;
            if (yy < 0 || yy > 63) continue;
            #pragma unroll
            for (int kx = 0; kx < 3; kx++) {
                int xk = xx + kx - 1;
                if (xk < 0 || xk > 63) continue;
                const float4 s = *(const float4*)(g_h + ((long)b * 4096 + yy * 64 + xk) * 1024 + ch0);
                acc[0] += s.x * w[ky][kx][0];
                acc[1] += s.y * w[ky][kx][1];
                acc[2] += s.z * w[ky][kx][2];
                acc[3] += s.w * w[ky][kx][3];
            }
        }
        float4 r;
        float v0 = acc[0] + bias4[0]; r.x = v0 * normcdff(v0);
        float v1 = acc[1] + bias4[1]; r.y = v1 * normcdff(v1);
        float v2 = acc[2] + bias4[2]; r.z = v2 * normcdff(v2);
        float v3 = acc[3] + bias4[3]; r.w = v3 * normcdff(v3);
        *(float4*)(g_h2 + ((long)b * 4096 + y * 64 + xx) * 1024 + ch0) = r;
    }
}

// ---------------------------------------------------------------------------
// Host launcher
// ---------------------------------------------------------------------------
extern "C" void kernel_launch(void* const* d_in, const int* in_sizes, int n_in,
                              void* d_out, int out_size)
{
    const float* x       = (const float*)d_in[0];
    const float* z       = (const float*)d_in[1];
    const float* mem     = (const float*)d_in[2];
    const float* cw      = (const float*)d_in[3];
    const float* p1      = (const float*)d_in[4];
    const float* tdt1    = (const float*)d_in[5];
    const float* p2      = (const float*)d_in[6];
    const float* tdt2    = (const float*)d_in[7];
    const float* sa      = (const float*)d_in[8];
    const float* sb      = (const float*)d_in[9];
    const float* q_w     = (const float*)d_in[10];
    const float* q_b     = (const float*)d_in[11];
    const float* k_w     = (const float*)d_in[12];
    const float* k_b     = (const float*)d_in[13];
    const float* v_w     = (const float*)d_in[14];
    const float* v_b     = (const float*)d_in[15];
    const float* proj_w  = (const float*)d_in[16];
    const float* proj_b  = (const float*)d_in[17];
    const float* norm_w  = (const float*)d_in[18];
    const float* norm_b  = (const float*)d_in[19];
    const float* fc1_w   = (const float*)d_in[20];
    const float* fc1_b   = (const float*)d_in[21];
    const float* dw_w    = (const float*)d_in[22];
    const float* dw_b    = (const float*)d_in[23];
    const float* fc2_w   = (const float*)d_in[24];
    const float* fc2_b   = (const float*)d_in[25];

    float* out  = (float*)d_out;                 // (B,N,C)
    float* out2 = out + 2097152l;                // cluster_x_z (B,nc,TN)
    float* out3 = out2 + 4915200l;               // assigned (B,T,nc,N)

    float *xf, *clT, *Abuf, *wcomb, *tmp, *soft, *cen, *cin, *kb, *vb, *qb, *ob, *opj, *o1, *hb, *h2, *h3;
    cudaGetSymbolAddress((void**)&xf,   g_xf);
    cudaGetSymbolAddress((void**)&clT,  g_clT);
    cudaGetSymbolAddress((void**)&Abuf, g_Abuf);
    cudaGetSymbolAddress((void**)&wcomb,g_wcomb);
    cudaGetSymbolAddress((void**)&tmp,  g_tmp);
    cudaGetSymbolAddress((void**)&soft, g_soft);
    cudaGetSymbolAddress((void**)&cen,  g_cen);
    cudaGetSymbolAddress((void**)&cin,  g_cin);
    cudaGetSymbolAddress((void**)&kb,   g_k);
    cudaGetSymbolAddress((void**)&vb,   g_v);
    cudaGetSymbolAddress((void**)&qb,   g_q);
    cudaGetSymbolAddress((void**)&ob,   g_o);
    cudaGetSymbolAddress((void**)&opj,  g_oproj);
    cudaGetSymbolAddress((void**)&o1,   g_out1);
    cudaGetSymbolAddress((void**)&hb,   g_h);
    cudaGetSymbolAddress((void**)&h2,   g_h2);
    cudaGetSymbolAddress((void**)&h3,   g_h3);

    const float qscale = 0.17677669529663687f;   // 1/sqrt(32)

    // 1. xf = concat(mem, x)
    build_xf<<<8192, 256>>>(x, mem);

    // 2. clT[bt][n][k] = xf[bt] @ cw^T  (M=4096, N=150, K=256, batch 8)
    fgemm<1,0><<<dim3(3, 32, 8), 256>>>(xf, cw, nullptr, clT,
        4096, 150, 256, 256, 256, 150, 4096l*256, 0l, 4096l*150, 1.f, 1, 256);

    // 3. cosine gates + Abuf
    cos_scale<<<dim3(512, 2), 256>>>(z, p1, p2);

    // 4. Wcomb = [tdt1; tdt2], ld=152
    build_wcomb<<<179, 256>>>(tdt1, tdt2);

    // 5. tmp = 0.5 * Abuf @ Wcomb  (M=16384, N=150, K=300, batch 2, ldb=152)
    fgemm<0,0><<<dim3(3, 128, 2), 256>>>(Abuf, wcomb, nullptr, tmp,
        16384, 150, 300, 300, 152, 150, 16384l*300, 0l, 16384l*150, 0.5f, 1, 300);

    // 6. transpose -> out2 (cluster_x_z), out3 (assigned/center)
    transpose_out<<<dim3(512, 5, 2), 256>>>(out2, out3);

    // 7. softmax over N -> g_soft
    softmax_rows<<<1200, 256>>>(out3);

    // 8. cen = soft @ xf  (M=150, N=256, K=4096, batch 8, split-K 8)
    zero_cen<<<300, 256>>>();
    fgemm<0,1><<<dim3(4, 2, 64), 256>>>(soft, xf, nullptr, cen,
        150, 256, 4096, 4096, 256, 256, 150l*4096, 4096l*256, 150l*256, 1.f, 8, 512);

    // 9. gate + C_in + LN
    gate_ln<<<dim3(150, 2), 256>>>(sa, sb, norm_w, norm_b);

    // 10/11. k, v projections (M=300)
    fgemm<1,0><<<dim3(4, 3, 1), 256>>>(cin, k_w, k_b, kb,
        300, 256, 256, 256, 256, 256, 0l, 0l, 0l, 1.f, 1, 256);
    fgemm<1,0><<<dim3(4, 3, 1), 256>>>(cin, v_w, v_b, vb,
        300, 256, 256, 256, 256, 256, 0l, 0l, 0l, 1.f, 1, 256);

    // 12. q projection (scaled)
    fgemm<1,0><<<dim3(4, 64, 1), 256>>>(x, q_w, q_b, qb,
        8192, 256, 256, 256, 256, 256, 0l, 0l, 0l, qscale, 1, 256);

    // 13. attention
    attn_kernel<<<dim3(128, 8, 2), 256>>>();

    // 14. output projection
    fgemm<1,0><<<dim3(4, 64, 1), 256>>>(ob, proj_w, proj_b, opj,
        8192, 256, 256, 256, 256, 256, 0l, 0l, 0l, 1.f, 1, 256);

    // 15. out1 = x + LN(oproj)
    add_ln<<<8192, 256>>>(x, opj, norm_w, norm_b, o1);

    // 16. fc1
    fgemm<1,0><<<dim3(16, 64, 1), 256>>>(o1, fc1_w, fc1_b, hb,
        8192, 1024, 256, 256, 256, 1024, 0l, 0l, 0l, 1.f, 1, 256);

    // 17. depthwise conv + bias + gelu
    dwconv<<<512, 256>>>(dw_w, dw_b);

    // 18. fc2
    fgemm<1,0><<<dim3(4, 64, 1), 256>>>(h2, fc2_w, fc2_b, h3,
        8192, 256, 1024, 1024, 1024, 256, 0l, 0l, 0l, 1.f, 1, 1024);

    // 19. final out = out1 + LN(h3)
    add_ln<<<8192, 256>>>(o1, h3, norm_w, norm_b, out);
}

// round 7
// speedup vs baseline: 2.4461x; 1.5516x over previous
#include <cuda_runtime.h>
#include <math.h>

// ---------------------------------------------------------------------------
// Problem constants (B=2, N=4096, C=256, nc=150, t=3 -> T=4, H=W=64, hid=1024)
// ---------------------------------------------------------------------------

// ---------------------------------------------------------------------------
// Scratch (allocation-free: __device__ globals)
// ---------------------------------------------------------------------------
__device__ float g_xf   [8l*4096*256];       // (B*T, N, C)
__device__ float g_clT  [8l*4096*150];       // (B*T, N, nc)
__device__ float g_Abuf [2l*16384*300];      // (B, TN, 300) = [z*g1 | cl*g2]
__device__ float g_wcomb[300*152 + 64];      // [tdt1; tdt2], ld=152
__device__ float g_tmp  [2l*16384*150];      // (B, TN, nc)
__device__ float g_soft [8l*150*4096];
__device__ float g_cen  [8l*150*256];
__device__ float g_cin  [2l*150*256];
__device__ float g_k    [2l*150*256];
__device__ float g_v    [2l*150*256];
__device__ float g_q    [2l*4096*256];
__device__ float g_o    [2l*4096*256];
__device__ float g_oproj[2l*4096*256];
__device__ float g_out1 [2l*4096*256];
__device__ float g_h    [2l*4096*1024];
__device__ float g_h2   [2l*4096*1024];
__device__ float g_h3   [2l*4096*256];

// ---------------------------------------------------------------------------
// bf16 split helpers (ALU-pipe bit ops, round-to-nearest-even)
// ---------------------------------------------------------------------------
__device__ __forceinline__ unsigned short f2bf(float x) {
    unsigned u = __float_as_uint(x);
    unsigned r = u + 0x7fffu + ((u >> 16) & 1u);
    return (unsigned short)(r >> 16);
}
__device__ __forceinline__ float bf2f(unsigned short x) {
    return __uint_as_float(((unsigned)x) << 16);
}
// permuted smem column for k index (within 32-k chunk):
// fragment (a0,a2) / (b0,b1) become ONE 64-bit LDS.
__device__ __forceinline__ int colOf(int kk) {
    return ((kk >> 4) << 4) + (((kk >> 1) & 3) << 2) + (kk & 1) + (((kk >> 3) & 1) << 1);
}

__device__ __forceinline__ void mma16816(float* d,
    unsigned a0, unsigned a1, unsigned a2, unsigned a3,
    unsigned b0, unsigned b1)
{
    asm("mma.sync.aligned.m16n8k16.row.col.f32.bf16.bf16.f32 "
        "{%0,%1,%2,%3}, {%4,%5,%6,%7}, {%8,%9}, {%0,%1,%2,%3};"
        : "+f"(d[0]), "+f"(d[1]), "+f"(d[2]), "+f"(d[3])
        : "r"(a0), "r"(a1), "r"(a2), "r"(a3), "r"(b0), "r"(b1));
}

// ---------------------------------------------------------------------------
// bf16-split tensor-core GEMM:  C = alpha * (A @ op(B) + bias)
//   TRANSB=1: B[n][k] (NT)    TRANSB=0: B[k][n] (NN)
//   ATOMIC=1: atomicAdd into C (split-K), bias ignored
// BM=128, BN=64, BK=32, 256 threads (8 warps: 4m x 2n), warp tile 32x32.
// hi/lo bf16 decomposition: acc = Ah@Bh + Ah@Bl + Al@Bh  (rel err ~1e-5)
// Requires lda%4==0, ldb%4==0.
// ---------------------------------------------------------------------------
template<int TRANSB, int ATOMIC>
__global__ __launch_bounds__(256) void bgemm(
    const float* __restrict__ A, const float* __restrict__ Bm,
    const float* __restrict__ bias, float* __restrict__ C,
    int M, int N, int K, int lda, int ldb, int ldc,
    long Astr, long Bstr, long Cstr, float alpha,
    int ksplit, int kLen)
{
    int zb = blockIdx.z;
    int batch = zb / ksplit;
    int ks = zb - batch * ksplit;
    int kStart = ks * kLen;
    int kEnd = kStart + kLen; if (kEnd > K) kEnd = K;

    A  += (long)batch * Astr;
    Bm += (long)batch * Bstr;
    C  += (long)batch * Cstr;

    __shared__ __align__(16) unsigned short Ah[128][48];
    __shared__ __align__(16) unsigned short Al[128][48];
    __shared__ __align__(16) unsigned short Bh[64][48];
    __shared__ __align__(16) unsigned short Bl[64][48];

    int m0 = blockIdx.y * 128, n0 = blockIdx.x * 64;
    int tid = threadIdx.x;
    int warp = tid >> 5, lane = tid & 31;
    int wm = (warp >> 1) * 32;      // 4 m-warps
    int wn = (warp & 1) * 32;       // 2 n-warps
    int g = lane >> 2, q = lane & 3;

    float acc[2][4][4];
    #pragma unroll
    for (int i = 0; i < 2; i++)
        #pragma unroll
        for (int j = 0; j < 4; j++)
            #pragma unroll
            for (int r = 0; r < 4; r++) acc[i][j][r] = 0.f;

    int nk = (kEnd - kStart + 31) >> 5;
    const float4 z4 = make_float4(0.f, 0.f, 0.f, 0.f);

    float4 pa[4], pb[2];

    // ---- load chunk kb into prefetch regs
    #define LOAD_CHUNK(kb)                                                     \
    {                                                                          \
        _Pragma("unroll")                                                      \
        for (int j = 0; j < 4; j++) {                                          \
            int i = tid + 256 * j;                                             \
            int row = i >> 3, kq = i & 7;                                      \
            int k = (kb) + kq * 4;                                             \
            int m = m0 + row;                                                  \
            pa[j] = (k < kEnd && m < M) ? *(const float4*)&A[(long)m * lda + k] : z4; \
        }                                                                      \
        _Pragma("unroll")                                                      \
        for (int j = 0; j < 2; j++) {                                          \
            int i = tid + 256 * j;                                             \
            if (TRANSB) {                                                      \
                int row = i >> 3, kq = i & 7;                                  \
                int k = (kb) + kq * 4;                                         \
                int n = n0 + row;                                              \
                pb[j] = (k < kEnd && n < N) ? *(const float4*)&Bm[(long)n * ldb + k] : z4; \
            } else {                                                           \
                int kr = i >> 4, n4 = i & 15;                                  \
                int k = (kb) + kr;                                             \
                pb[j] = (k < kEnd) ? *(const float4*)&Bm[(long)k * ldb + n0 + n4 * 4] : z4; \
            }                                                                  \
        }                                                                      \
    }

    // ---- convert prefetch regs to hi/lo bf16 and store to smem
    #define STORE_CHUNK()                                                      \
    {                                                                          \
        _Pragma("unroll")                                                      \
        for (int j = 0; j < 4; j++) {                                          \
            int i = tid + 256 * j;                                             \
            int row = i >> 3, kq = i & 7;                                      \
            int kk0 = kq * 4;                                                  \
            float v[4] = {pa[j].x, pa[j].y, pa[j].z, pa[j].w};                 \
            unsigned short h[4], l[4];                                         \
            _Pragma("unroll")                                                  \
            for (int e = 0; e < 4; e++) {                                      \
                h[e] = f2bf(v[e]);                                             \
                l[e] = f2bf(v[e] - bf2f(h[e]));                                \
            }                                                                  \
            int c01 = colOf(kk0), c23 = colOf(kk0 + 2);                        \
            *(ushort2*)&Ah[row][c01] = make_ushort2(h[0], h[1]);               \
            *(ushort2*)&Ah[row][c23] = make_ushort2(h[2], h[3]);               \
            *(ushort2*)&Al[row][c01] = make_ushort2(l[0], l[1]);               \
            *(ushort2*)&Al[row][c23] = make_ushort2(l[2], l[3]);               \
        }                                                                      \
        _Pragma("unroll")                                                      \
        for (int j = 0; j < 2; j++) {                                          \
            int i = tid + 256 * j;                                             \
            if (TRANSB) {                                                      \
                int row = i >> 3, kq = i & 7;                                  \
                int kk0 = kq * 4;                                              \
                float v[4] = {pb[j].x, pb[j].y, pb[j].z, pb[j].w};             \
                unsigned short h[4], l[4];                                     \
                _Pragma("unroll")                                              \
                for (int e = 0; e < 4; e++) {                                  \
                    h[e] = f2bf(v[e]);                                         \
                    l[e] = f2bf(v[e] - bf2f(h[e]));                            \
                }                                                              \
                int c01 = colOf(kk0), c23 = colOf(kk0 + 2);                    \
                *(ushort2*)&Bh[row][c01] = make_ushort2(h[0], h[1]);           \
                *(ushort2*)&Bh[row][c23] = make_ushort2(h[2], h[3]);           \
                *(ushort2*)&Bl[row][c01] = make_ushort2(l[0], l[1]);           \
                *(ushort2*)&Bl[row][c23] = make_ushort2(l[2], l[3]);           \
            } else {                                                           \
                int kr = i >> 4, n4 = i & 15;                                  \
                int c = colOf(kr);                                             \
                float v[4] = {pb[j].x, pb[j].y, pb[j].z, pb[j].w};             \
                _Pragma("unroll")                                              \
                for (int e = 0; e < 4; e++) {                                  \
                    int n = n4 * 4 + e;                                        \
                    unsigned short h = f2bf(v[e]);                             \
                    Bh[n][c] = h;                                              \
                    Bl[n][c] = f2bf(v[e] - bf2f(h));                           \
                }                                                              \
            }                                                                  \
        }                                                                      \
    }

    LOAD_CHUNK(kStart);
    STORE_CHUNK();
    __syncthreads();

    for (int c = 0; c < nk; c++) {
        if (c + 1 < nk) LOAD_CHUNK(kStart + (c + 1) * 32);

        #pragma unroll
        for (int s = 0; s < 2; s++) {
            int cb = s * 16 + q * 4;
            uint2 ah[2][2], al[2][2];
            #pragma unroll
            for (int tm = 0; tm < 2; tm++) {
                int r0 = wm + tm * 16 + g;
                ah[tm][0] = *(const uint2*)&Ah[r0][cb];
                ah[tm][1] = *(const uint2*)&Ah[r0 + 8][cb];
                al[tm][0] = *(const uint2*)&Al[r0][cb];
                al[tm][1] = *(const uint2*)&Al[r0 + 8][cb];
            }
            uint2 bh[4], bl[4];
            #pragma unroll
            for (int tn = 0; tn < 4; tn++) {
                int rn = wn + tn * 8 + g;
                bh[tn] = *(const uint2*)&Bh[rn][cb];
                bl[tn] = *(const uint2*)&Bl[rn][cb];
            }
            #pragma unroll
            for (int tm = 0; tm < 2; tm++)
                #pragma unroll
                for (int tn = 0; tn < 4; tn++) {
                    float* d = acc[tm][tn];
                    mma16816(d, ah[tm][0].x, ah[tm][1].x, ah[tm][0].y, ah[tm][1].y,
                             bh[tn].x, bh[tn].y);
                    mma16816(d, ah[tm][0].x, ah[tm][1].x, ah[tm][0].y, ah[tm][1].y,
                             bl[tn].x, bl[tn].y);
                    mma16816(d, al[tm][0].x, al[tm][1].x, al[tm][0].y, al[tm][1].y,
                             bh[tn].x, bh[tn].y);
                }
        }
        __syncthreads();
        if (c + 1 < nk) {
            STORE_CHUNK();
            __syncthreads();
        }
    }

    // epilogue
    #pragma unroll
    for (int tm = 0; tm < 2; tm++) {
        int mA = m0 + wm + tm * 16 + g;
        #pragma unroll
        for (int tn = 0; tn < 4; tn++) {
            int n1 = n0 + wn + tn * 8 + 2 * q;
            float* d = acc[tm][tn];
            #pragma unroll
            for (int half = 0; half < 2; half++) {
                int m = mA + half * 8;
                if (m >= M) continue;
                float v0 = d[half * 2 + 0], v1 = d[half * 2 + 1];
                if (ATOMIC) {
                    if (n1 < N)     atomicAdd(&C[(long)m * ldc + n1],     v0 * alpha);
                    if (n1 + 1 < N) atomicAdd(&C[(long)m * ldc + n1 + 1], v1 * alpha);
                } else {
                    if (n1 < N)
                        C[(long)m * ldc + n1] = (v0 + (bias ? bias[n1] : 0.f)) * alpha;
                    if (n1 + 1 < N)
                        C[(long)m * ldc + n1 + 1] = (v1 + (bias ? bias[n1 + 1] : 0.f)) * alpha;
                }
            }
        }
    }
    #undef LOAD_CHUNK
    #undef STORE_CHUNK
}

// ---------------------------------------------------------------------------
// Block reductions (blockDim.x == 256)
// ---------------------------------------------------------------------------
__device__ __forceinline__ float blockReduceSum(float v, float* sh) {
    __syncthreads();
    int lane = threadIdx.x & 31, w = threadIdx.x >> 5;
    #pragma unroll
    for (int o = 16; o; o >>= 1) v += __shfl_xor_sync(0xffffffffu, v, o);
    if (lane == 0) sh[w] = v;
    __syncthreads();
    if (w == 0) {
        float t = (lane < 8) ? sh[lane] : 0.f;
        #pragma unroll
        for (int o = 4; o; o >>= 1) t += __shfl_xor_sync(0xffffffffu, t, o);
        if (lane == 0) sh[0] = t;
    }
    __syncthreads();
    return sh[0];
}

__device__ __forceinline__ float blockReduceMax(float v, float* sh) {
    __syncthreads();
    int lane = threadIdx.x & 31, w = threadIdx.x >> 5;
    #pragma unroll
    for (int o = 16; o; o >>= 1) v = fmaxf(v, __shfl_xor_sync(0xffffffffu, v, o));
    if (lane == 0) sh[w] = v;
    __syncthreads();
    if (w == 0) {
        float t = (lane < 8) ? sh[lane] : -1e30f;
        #pragma unroll
        for (int o = 4; o; o >>= 1) t = fmaxf(t, __shfl_xor_sync(0xffffffffu, t, o));
        if (lane == 0) sh[0] = t;
    }
    __syncthreads();
    return sh[0];
}

// ---------------------------------------------------------------------------
// build xf = concat(mem, x) as (B*T, N, C)
// ---------------------------------------------------------------------------
__global__ void build_xf(const float* __restrict__ x, const float* __restrict__ mem) {
    long f = (long)blockIdx.x * blockDim.x + threadIdx.x;
    if (f >= 2097152l) return;
    long bt = f / 262144l;
    long rem = f - bt * 262144l;
    long b = bt >> 2, ti = bt & 3;
    const float4* src;
    if (ti < 3) src = (const float4*)mem + (b*3 + ti) * 262144l + rem;
    else        src = (const float4*)x   + b * 262144l + rem;
    ((float4*)g_xf)[f] = *src;
}

// ---------------------------------------------------------------------------
// cosine gates + build Abuf (B, TN, 300) = [z*g1 | clT*g2]
// ---------------------------------------------------------------------------
__global__ __launch_bounds__(256) void cos_scale(
    const float* __restrict__ z, const float* __restrict__ p1, const float* __restrict__ p2)
{
    __shared__ float sz[150][32];
    __shared__ float scl[32][161];
    __shared__ float g1[32], g2[32];
    int b = blockIdx.y;
    int m0 = blockIdx.x * 32;
    int ti = m0 >> 12, nn0 = m0 & 4095;
    for (int i = threadIdx.x; i < 150 * 32; i += 256) {
        int kk = i >> 5, mm = i & 31;
        sz[kk][mm] = z[((long)b * 150 + kk) * 16384l + m0 + mm];
    }
    for (int i = threadIdx.x; i < 32 * 160; i += 256) {
        int mm = i / 160, col = i - mm * 160;
        if (col < 150)
            scl[mm][col] = g_clT[(((long)(b * 4 + ti)) * 4096 + nn0 + mm) * 150 + col];
    }
    __syncthreads();
    if (threadIdx.x < 32) {
        int mm = threadIdx.x;
        float dz = 0, zz = 0, dc = 0, cc = 0, pp1 = 0, pp2 = 0;
        for (int kk = 0; kk < 150; kk++) {
            float zv = sz[kk][mm], cv = scl[mm][kk];
            float a = p1[kk], bb = p2[kk];
            dz += zv * a; zz += zv * zv;
            dc += cv * bb; cc += cv * cv;
            pp1 += a * a; pp2 += bb * bb;
        }
        float c1 = dz / (fmaxf(sqrtf(zz), 1e-12f) * fmaxf(sqrtf(pp1), 1e-12f));
        float c2 = dc / (fmaxf(sqrtf(cc), 1e-12f) * fmaxf(sqrtf(pp2), 1e-12f));
        g1[mm] = fminf(fmaxf(c1, 0.f), 1.f);
        g2[mm] = fminf(fmaxf(c2, 0.f), 1.f);
    }
    __syncthreads();
    for (int i = threadIdx.x; i < 32 * 300; i += 256) {
        int mm = i / 300, kk = i - mm * 300;
        float v = (kk < 150) ? sz[kk][mm] * g1[mm] : scl[mm][kk - 150] * g2[mm];
        g_Abuf[(((long)b * 16384l) + m0 + mm) * 300 + kk] = v;
    }
}

// wcomb with ld=152 (zero-padded cols 150..151 and 64-float tail)
__global__ void build_wcomb(const float* __restrict__ t1, const float* __restrict__ t2) {
    int i = blockIdx.x * blockDim.x + threadIdx.x;
    if (i >= 300 * 152 + 64) return;
    float v = 0.f;
    if (i < 300 * 152) {
        int row = i / 152, col = i - row * 152;
        if (col < 150)
            v = (row < 150) ? t1[row * 150 + col] : t2[(row - 150) * 150 + col];
    }
    g_wcomb[i] = v;
}

__global__ void zero_cen() {
    int i = blockIdx.x * 256 + threadIdx.x;
    if (i < 76800) ((float4*)g_cen)[i] = make_float4(0.f, 0.f, 0.f, 0.f);
}

// ---------------------------------------------------------------------------
// transpose tmp (B,TN,nc) -> out2 (B,nc,TN) and out3 (B,T,nc,N)
// ---------------------------------------------------------------------------
__global__ __launch_bounds__(256) void transpose_out(float* __restrict__ out2, float* __restrict__ out3) {
    __shared__ float t[32][33];
    int b = blockIdx.z;
    int m0 = blockIdx.x * 32;
    int j0 = blockIdx.y * 32;
    int tx = threadIdx.x & 31, ty = threadIdx.x >> 5;
    for (int i = ty; i < 32; i += 8) {
        int j = j0 + tx;
        t[i][tx] = (j < 150) ? g_tmp[((long)b * 16384l + m0 + i) * 150 + j] : 0.f;
    }
    __syncthreads();
    for (int i = ty; i < 32; i += 8) {
        int j = j0 + i;
        if (j < 150) {
            int m = m0 + tx;
            float v = t[tx][i];
            out2[((long)b * 150 + j) * 16384l + m] = v;
            int ti = m >> 12, n = m & 4095;
            out3[(((long)(b * 4 + ti)) * 150 + j) * 4096l + n] = v;
        }
    }
}

// ---------------------------------------------------------------------------
// row softmax (1200 rows of 4096)
// ---------------------------------------------------------------------------
__global__ __launch_bounds__(256) void softmax_rows(const float* __restrict__ in) {
    __shared__ float sh[32];
    long row = blockIdx.x;
    const float* p = in + row * 4096l;
    float mx = -1e30f;
    for (int i = threadIdx.x; i < 4096; i += 256) mx = fmaxf(mx, p[i]);
    mx = blockReduceMax(mx, sh);
    float s = 0.f;
    for (int i = threadIdx.x; i < 4096; i += 256) s += __expf(p[i] - mx);
    s = blockReduceSum(s, sh);
    float inv = 1.f / s;
    float* qq = g_soft + row * 4096l;
    for (int i = threadIdx.x; i < 4096; i += 256) qq[i] = __expf(p[i] - mx) * inv;
}

// ---------------------------------------------------------------------------
// gate + C_in + LN  -> g_cin
// ---------------------------------------------------------------------------
__global__ __launch_bounds__(256) void gate_ln(
    const float* __restrict__ sa, const float* __restrict__ sb,
    const float* __restrict__ nw, const float* __restrict__ nb)
{
    __shared__ float sh[32];
    int b = blockIdx.y, k = blockIdx.x, c = threadIdx.x;
    const float* base = g_cen + ((long)(b * 4) * 150 + k) * 256;
    float l = base[3l * 150 * 256 + c];
    float p0 = base[0l * 150 * 256 + c];
    float p1v = base[1l * 150 * 256 + c];
    float p2v = base[2l * 150 * 256 + c];
    float alpha = sa[0], beta = sb[0];
    float ll = blockReduceSum(l * l, sh);
    float nl = sqrtf(ll);
    float g[3];
    float pv[3] = {p0, p1v, p2v};
    #pragma unroll
    for (int ti = 0; ti < 3; ti++) {
        float d  = blockReduceSum(l * pv[ti], sh);
        float nn = blockReduceSum(pv[ti] * pv[ti], sh);
        float denom = fmaxf(nl * sqrtf(nn), 1e-8f);
        float a = beta + alpha * (d / denom);
        g[ti] = 1.f / (1.f + expf(-a));
    }
    float v = l + g[0] * p0 + g[1] * p1v + g[2] * p2v;
    float mean = blockReduceSum(v, sh) * (1.f / 256.f);
    float dlt = v - mean;
    float var = blockReduceSum(dlt * dlt, sh) * (1.f / 256.f);
    g_cin[((long)b * 150 + k) * 256 + c] = dlt * rsqrtf(var + 1e-5f) * nw[c] + nb[c];
}

// ---------------------------------------------------------------------------
// attention (8 heads, nc=150 keys). grid (N/32, 8, B), block 256
// ---------------------------------------------------------------------------
__global__ __launch_bounds__(256) void attn_kernel() {
    __shared__ float sk[150][33];
    __shared__ float sv[150][32];
    __shared__ float sq[32][32];
    __shared__ float sp[8][150];
    int b = blockIdx.z, h = blockIdx.y;
    int n0 = blockIdx.x * 32;
    int tid = threadIdx.x;
    for (int i = tid; i < 150 * 32; i += 256) {
        int kk = i >> 5, d = i & 31;
        long off = ((long)b * 150 + kk) * 256 + h * 32 + d;
        sk[kk][d] = g_k[off];
        sv[kk][d] = g_v[off];
    }
    for (int i = tid; i < 1024; i += 256) {
        int nn = i >> 5, d = i & 31;
        sq[nn][d] = g_q[((long)(b * 4096) + n0 + nn) * 256 + h * 32 + d];
    }
    __syncthreads();
    int w = tid >> 5, lane = tid & 31;
    for (int nn = w; nn < 32; nn += 8) {
        float e[5];
        float mx = -1e30f;
        #pragma unroll
        for (int s = 0; s < 5; s++) {
            int kk = lane + s * 32;
            float dot = -1e30f;
            if (kk < 150) {
                dot = 0.f;
                #pragma unroll
                for (int d = 0; d < 32; d++) dot += sq[nn][d] * sk[kk][d];
            }
            e[s] = dot;
            mx = fmaxf(mx, dot);
        }
        #pragma unroll
        for (int o = 16; o; o >>= 1) mx = fmaxf(mx, __shfl_xor_sync(0xffffffffu, mx, o));
        float sum = 0.f;
        #pragma unroll
        for (int s = 0; s < 5; s++) {
            int kk = lane + s * 32;
            float ev = (kk < 150) ? __expf(e[s] - mx) : 0.f;
            e[s] = ev;
            sum += ev;
        }
        #pragma unroll
        for (int o = 16; o; o >>= 1) sum += __shfl_xor_sync(0xffffffffu, sum, o);
        float inv = 1.f / sum;
        #pragma unroll
        for (int s = 0; s < 5; s++) {
            int kk = lane + s * 32;
            if (kk < 150) sp[w][kk] = e[s] * inv;
        }
        __syncwarp();
        float acc = 0.f;
        for (int kk = 0; kk < 150; kk++) acc += sp[w][kk] * sv[kk][lane];
        g_o[((long)(b * 4096) + n0 + nn) * 256 + h * 32 + lane] = acc;
        __syncwarp();
    }
}

// ---------------------------------------------------------------------------
// out = resid + LN(xin)   (rows of 256)
// ---------------------------------------------------------------------------
__global__ __launch_bounds__(256) void add_ln(
    const float* __restrict__ resid, const float* __restrict__ xin,
    const float* __restrict__ nw, const float* __restrict__ nb, float* __restrict__ out)
{
    __shared__ float sh[32];
    long row = blockIdx.x;
    float v = xin[row * 256 + threadIdx.x];
    float mean = blockReduceSum(v, sh) * (1.f / 256.f);
    float d = v - mean;
    float var = blockReduceSum(d * d, sh) * (1.f / 256.f);
    out[row * 256 + threadIdx.x] =
        resid[row * 256 + threadIdx.x] + d * rsqrtf(var + 1e-5f) * nw[threadIdx.x] + nb[threadIdx.x];
}

// ---------------------------------------------------------------------------
// depthwise 3x3 conv (SAME) on (B,1024,64,64) + bias + exact GELU
// ---------------------------------------------------------------------------
__global__ __launch_bounds__(256) void dwconv(
    const float* __restrict__ dw, const float* __restrict__ dwb)
{
    int blk = blockIdx.x;
    int b = blk >> 8;
    int chunk = blk & 255;
    int y = chunk >> 2;
    int x0 = (chunk & 3) * 16;
    int ch0 = threadIdx.x * 4;
    float w[3][3][4];
    #pragma unroll
    for (int ky = 0; ky < 3; ky++)
        #pragma unroll
        for (int kx = 0; kx < 3; kx++)
            #pragma unroll
            for (int c = 0; c < 4; c++)
                w[ky][kx][c] = dw[(long)(ch0 + c) * 9 + ky * 3 + kx];
    float bias4[4];
    #pragma unroll
    for (int c = 0; c < 4; c++) bias4[c] = dwb[ch0 + c];
    for (int xi = 0; xi < 16; xi++) {
        int xx = x0 + xi;
        float acc[4] = {0.f, 0.f, 0.f, 0.f};
        #pragma unroll
        for (int ky = 0; ky < 3; ky++) {
            int yy = y + ky - 1;
            if (yy < 0 || yy > 63) continue;
            #pragma unroll
            for (int kx = 0; kx < 3; kx++) {
                int xk = xx + kx - 1;
                if (xk < 0 || xk > 63) continue;
                const float4 s = *(const float4*)(g_h + ((long)b * 4096 + yy * 64 + xk) * 1024 + ch0);
                acc[0] += s.x * w[ky][kx][0];
                acc[1] += s.y * w[ky][kx][1];
                acc[2] += s.z * w[ky][kx][2];
                acc[3] += s.w * w[ky][kx][3];
            }
        }
        float4 r;
        float v0 = acc[0] + bias4[0]; r.x = v0 * normcdff(v0);
        float v1 = acc[1] + bias4[1]; r.y = v1 * normcdff(v1);
        float v2 = acc[2] + bias4[2]; r.z = v2 * normcdff(v2);
        float v3 = acc[3] + bias4[3]; r.w = v3 * normcdff(v3);
        *(float4*)(g_h2 + ((long)b * 4096 + y * 64 + xx) * 1024 + ch0) = r;
    }
}

// ---------------------------------------------------------------------------
// Host launcher
// ---------------------------------------------------------------------------
extern "C" void kernel_launch(void* const* d_in, const int* in_sizes, int n_in,
                              void* d_out, int out_size)
{
    const float* x       = (const float*)d_in[0];
    const float* z       = (const float*)d_in[1];
    const float* mem     = (const float*)d_in[2];
    const float* cw      = (const float*)d_in[3];
    const float* p1      = (const float*)d_in[4];
    const float* tdt1    = (const float*)d_in[5];
    const float* p2      = (const float*)d_in[6];
    const float* tdt2    = (const float*)d_in[7];
    const float* sa      = (const float*)d_in[8];
    const float* sb      = (const float*)d_in[9];
    const float* q_w     = (const float*)d_in[10];
    const float* q_b     = (const float*)d_in[11];
    const float* k_w     = (const float*)d_in[12];
    const float* k_b     = (const float*)d_in[13];
    const float* v_w     = (const float*)d_in[14];
    const float* v_b     = (const float*)d_in[15];
    const float* proj_w  = (const float*)d_in[16];
    const float* proj_b  = (const float*)d_in[17];
    const float* norm_w  = (const float*)d_in[18];
    const float* norm_b  = (const float*)d_in[19];
    const float* fc1_w   = (const float*)d_in[20];
    const float* fc1_b   = (const float*)d_in[21];
    const float* dw_w    = (const float*)d_in[22];
    const float* dw_b    = (const float*)d_in[23];
    const float* fc2_w   = (const float*)d_in[24];
    const float* fc2_b   = (const float*)d_in[25];

    float* out  = (float*)d_out;                 // (B,N,C)
    float* out2 = out + 2097152l;                // cluster_x_z (B,nc,TN)
    float* out3 = out2 + 4915200l;               // assigned (B,T,nc,N)

    float *xf, *clT, *Abuf, *wcomb, *tmp, *soft, *cen, *cin, *kb, *vb, *qb, *ob, *opj, *o1, *hb, *h2, *h3;
    cudaGetSymbolAddress((void**)&xf,   g_xf);
    cudaGetSymbolAddress((void**)&clT,  g_clT);
    cudaGetSymbolAddress((void**)&Abuf, g_Abuf);
    cudaGetSymbolAddress((void**)&wcomb,g_wcomb);
    cudaGetSymbolAddress((void**)&tmp,  g_tmp);
    cudaGetSymbolAddress((void**)&soft, g_soft);
    cudaGetSymbolAddress((void**)&cen,  g_cen);
    cudaGetSymbolAddress((void**)&cin,  g_cin);
    cudaGetSymbolAddress((void**)&kb,   g_k);
    cudaGetSymbolAddress((void**)&vb,   g_v);
    cudaGetSymbolAddress((void**)&qb,   g_q);
    cudaGetSymbolAddress((void**)&ob,   g_o);
    cudaGetSymbolAddress((void**)&opj,  g_oproj);
    cudaGetSymbolAddress((void**)&o1,   g_out1);
    cudaGetSymbolAddress((void**)&hb,   g_h);
    cudaGetSymbolAddress((void**)&h2,   g_h2);
    cudaGetSymbolAddress((void**)&h3,   g_h3);

    const float qscale = 0.17677669529663687f;   // 1/sqrt(32)

    // 1. xf = concat(mem, x)
    build_xf<<<8192, 256>>>(x, mem);

    // 2. clT[bt][n][k] = xf[bt] @ cw^T  (M=4096, N=150, K=256, batch 8)
    bgemm<1,0><<<dim3(3, 32, 8), 256>>>(xf, cw, nullptr, clT,
        4096, 150, 256, 256, 256, 150, 4096l*256, 0l, 4096l*150, 1.f, 1, 256);

    // 3. cosine gates + Abuf
    cos_scale<<<dim3(512, 2), 256>>>(z, p1, p2);

    // 4. Wcomb = [tdt1; tdt2], ld=152
    build_wcomb<<<179, 256>>>(tdt1, tdt2);

    // 5. tmp = 0.5 * Abuf @ Wcomb  (M=16384, N=150, K=300, batch 2, ldb=152)
    bgemm<0,0><<<dim3(3, 128, 2), 256>>>(Abuf, wcomb, nullptr, tmp,
        16384, 150, 300, 300, 152, 150, 16384l*300, 0l, 16384l*150, 0.5f, 1, 300);

    // 6. transpose -> out2 (cluster_x_z), out3 (assigned/center)
    transpose_out<<<dim3(512, 5, 2), 256>>>(out2, out3);

    // 7. softmax over N -> g_soft
    softmax_rows<<<1200, 256>>>(out3);

    // 8. cen = soft @ xf  (M=150, N=256, K=4096, batch 8, split-K 8)
    zero_cen<<<300, 256>>>();
    bgemm<0,1><<<dim3(4, 2, 64), 256>>>(soft, xf, nullptr, cen,
        150, 256, 4096, 4096, 256, 256, 150l*4096, 4096l*256, 150l*256, 1.f, 8, 512);

    // 9. gate + C_in + LN
    gate_ln<<<dim3(150, 2), 256>>>(sa, sb, norm_w, norm_b);

    // 10/11. k, v projections (M=300)
    bgemm<1,0><<<dim3(4, 3, 1), 256>>>(cin, k_w, k_b, kb,
        300, 256, 256, 256, 256, 256, 0l, 0l, 0l, 1.f, 1, 256);
    bgemm<1,0><<<dim3(4, 3, 1), 256>>>(cin, v_w, v_b, vb,
        300, 256, 256, 256, 256, 256, 0l, 0l, 0l, 1.f, 1, 256);

    // 12. q projection (scaled)
    bgemm<1,0><<<dim3(4, 64, 1), 256>>>(x, q_w, q_b, qb,
        8192, 256, 256, 256, 256, 256, 0l, 0l, 0l, qscale, 1, 256);

    // 13. attention
    attn_kernel<<<dim3(128, 8, 2), 256>>>();

    // 14. output projection
    bgemm<1,0><<<dim3(4, 64, 1), 256>>>(ob, proj_w, proj_b, opj,
        8192, 256, 256, 256, 256, 256, 0l, 0l, 0l, 1.f, 1, 256);

    // 15. out1 = x + LN(oproj)
    add_ln<<<8192, 256>>>(x, opj, norm_w, norm_b, o1);

    // 16. fc1
    bgemm<1,0><<<dim3(16, 64, 1), 256>>>(o1, fc1_w, fc1_b, hb,
        8192, 1024, 256, 256, 256, 1024, 0l, 0l, 0l, 1.f, 1, 256);

    // 17. depthwise conv + bias + gelu
    dwconv<<<512, 256>>>(dw_w, dw_b);

    // 18. fc2
    bgemm<1,0><<<dim3(4, 64, 1), 256>>>(h2, fc2_w, fc2_b, h3,
        8192, 256, 1024, 1024, 1024, 256, 0l, 0l, 0l, 1.f, 1, 1024);

    // 19. final out = out1 + LN(h3)
    add_ln<<<8192, 256>>>(o1, h3, norm_w, norm_b, out);
}